// round 9
// baseline (speedup 1.0000x reference)
#include <cuda_runtime.h>

#define NSTATE (1u << 22)

typedef unsigned long long ull;

// packed unit: 2 complex amplitudes (2k, 2k+1) as rp=(r0,r1), ip=(i0,i1)
struct UP { ull rp, ip; };

__device__ __forceinline__ ull pk2(float x, float y) {
    ull d;
    asm("mov.b64 %0, {%1, %2};" : "=l"(d)
        : "r"(__float_as_uint(x)), "r"(__float_as_uint(y)));
    return d;
}
__device__ __forceinline__ ull pkdup(float x) { return pk2(x, x); }
__device__ __forceinline__ ull pkmul(ull a, ull b) {
    ull d; asm("mul.rn.f32x2 %0, %1, %2;" : "=l"(d) : "l"(a), "l"(b)); return d;
}
__device__ __forceinline__ ull pkfma(ull a, ull b, ull c) {
    ull d; asm("fma.rn.f32x2 %0, %1, %2, %3;" : "=l"(d) : "l"(a), "l"(b), "l"(c));
    return d;
}

// packed butterfly on a unit pair (A = bit0 side, B = bit1 side):
// 2 complex butterflies in 8 packed instructions.
__device__ __forceinline__ void gateP(UP& A, UP& B, ull c2, ull s2, ull n2)
{
    ull ar = pkfma(s2, B.ip, pkmul(c2, A.rp));
    ull ai = pkfma(n2, B.rp, pkmul(c2, A.ip));
    ull br = pkfma(s2, A.ip, pkmul(c2, B.rp));
    ull bi = pkfma(n2, A.rp, pkmul(c2, B.ip));
    A.rp = ar; A.ip = ai; B.rp = br; B.ip = bi;
}

// scalar butterfly (only for gateA's intra-unit bit 0)
__device__ __forceinline__ void gate1(float& r0, float& i0, float& r1, float& i1,
                                      float c, float s)
{
    float nr0 = c * r0 + s * i1;
    float ni0 = c * i0 - s * r1;
    float nr1 = c * r1 + s * i0;
    float ni1 = c * i1 - s * r0;
    r0 = nr0; i0 = ni0; r1 = nr1; i1 = ni1;
}

// swizzle on unit index: bank-column = (u ^ (u>>3)) & 7
__device__ __forceinline__ int SW(int u) { return u ^ ((u >> 3) & 7); }

// half-CTA named barrier (ids 1,2; 256 threads each)
#define BAR_HALF(t) asm volatile("bar.sync %0, 256;" :: "r"(1 + ((t) >> 8)) : "memory")

// per-CTA coefficient table: sc[a]=cos(angle[a]/2), ss[a]=sin(angle[a]/2).
// Complex bit b uses angle index 21-b.
#define MAKE_COEFS(ang, sc, ss, t)                                            \
    do {                                                                      \
        if ((t) < 22) {                                                       \
            float c_, s_;                                                     \
            sincosf(0.5f * __ldg((ang) + (t)), &s_, &c_);                     \
            (sc)[t] = c_; (ss)[t] = s_;                                       \
        }                                                                     \
    } while (0)

// packed 3-stage butterfly network over 8 units, reg-bit strides m0<m1<m2,
// angle indices a0,a1,a2 read from smem coef tables sc/ss.
#define STAGE(MASK, AIDX)                                                     \
    do {                                                                      \
        ull c2 = pkdup(sc[AIDX]), s2 = pkdup(ss[AIDX]), n2 = pkdup(-ss[AIDX]);\
        _Pragma("unroll")                                                     \
        for (int p_ = 0; p_ < 8; ++p_)                                        \
            if (!(p_ & (MASK))) gateP(U[p_], U[p_ | (MASK)], c2, s2, n2);     \
    } while (0)

// ---------------------------------------------------------------------------
// Kernel A: gates on complex bits 0..12 (angles 21..9).
// Tile = 8192 contiguous complex (64KB smem, 4096 units). 512 threads.
// Phases: fill(bits 0-3) |h| R2(4-6) |h| R3(7-9) |F| drain(10-12)+store.
// ---------------------------------------------------------------------------
__global__ void __launch_bounds__(512, 2) gateA(const float* __restrict__ xr,
                                                const float* __restrict__ xi,
                                                const float* __restrict__ ang,
                                                float* __restrict__ outr,
                                                float* __restrict__ outi)
{
    extern __shared__ ulonglong2 sm[];        // 4096 units = 64KB
    __shared__ float sc[22], ss[22];
    const int t = threadIdx.x;
    const unsigned base = (unsigned)blockIdx.x << 13;

    MAKE_COEFS(ang, sc, ss, t);

    UP U[8];

    // ---- fill: 16 contiguous complex/thread, gate bits 0..3 ----
    {
        float4 R[4], I[4];
        const float4* pr = reinterpret_cast<const float4*>(xr + base) + t * 4;
        const float4* pi = reinterpret_cast<const float4*>(xi + base) + t * 4;
#pragma unroll
        for (int q = 0; q < 4; ++q) { R[q] = pr[q]; I[q] = pi[q]; }

        __syncthreads();                      // coefs ready (after LDG issue)

        float c0 = sc[21], s0 = ss[21];
#pragma unroll
        for (int q = 0; q < 4; ++q) {         // bit 0 (intra-unit, scalar)
            gate1(R[q].x, I[q].x, R[q].y, I[q].y, c0, s0);
            gate1(R[q].z, I[q].z, R[q].w, I[q].w, c0, s0);
        }
        // pack: unit m = 2q+h holds complex (4q+2h, 4q+2h+1)
#pragma unroll
        for (int q = 0; q < 4; ++q) {
            U[2*q].rp   = pk2(R[q].x, R[q].y); U[2*q].ip   = pk2(I[q].x, I[q].y);
            U[2*q+1].rp = pk2(R[q].z, R[q].w); U[2*q+1].ip = pk2(I[q].z, I[q].w);
        }
        STAGE(1, 20);                         // bit 1
        STAGE(2, 19);                         // bit 2
        STAGE(4, 18);                         // bit 3
#pragma unroll
        for (int m = 0; m < 8; ++m)
            sm[SW(t * 8 + m)] = make_ulonglong2(U[m].rp, U[m].ip);
    }
    BAR_HALF(t);

    // ---- R2: gates bits 4-6 (unit bits 3-5), angles 17,16,15 ----
    {
        const int lo = t & 7, hi = t >> 3;
#pragma unroll
        for (int j = 0; j < 8; ++j) {
            ulonglong2 v = sm[SW((hi << 6) | (j << 3) | lo)];
            U[j].rp = v.x; U[j].ip = v.y;
        }
        STAGE(1, 17); STAGE(2, 16); STAGE(4, 15);
#pragma unroll
        for (int j = 0; j < 8; ++j)
            sm[SW((hi << 6) | (j << 3) | lo)] = make_ulonglong2(U[j].rp, U[j].ip);
    }
    BAR_HALF(t);

    // ---- R3: gates bits 7-9 (unit bits 6-8), angles 14,13,12 ----
    {
        const int lo = t & 63, hi = t >> 6;
#pragma unroll
        for (int j = 0; j < 8; ++j) {
            ulonglong2 v = sm[SW((hi << 9) | (j << 6) | lo)];
            U[j].rp = v.x; U[j].ip = v.y;
        }
        STAGE(1, 14); STAGE(2, 13); STAGE(4, 12);
#pragma unroll
        for (int j = 0; j < 8; ++j)
            sm[SW((hi << 9) | (j << 6) | lo)] = make_ulonglong2(U[j].rp, U[j].ip);
    }
    __syncthreads();                          // drain crosses CTA halves

    // ---- drain: gates bits 10-12 (unit bits 9-11), angles 11,10,9; store ----
    {
#pragma unroll
        for (int j = 0; j < 8; ++j) {
            ulonglong2 v = sm[SW((j << 9) | t)];
            U[j].rp = v.x; U[j].ip = v.y;
        }
        STAGE(1, 11); STAGE(2, 10); STAGE(4, 9);
#pragma unroll
        for (int j = 0; j < 8; ++j) {
            unsigned c = base + ((unsigned)j << 10) + 2u * (unsigned)t;
            *reinterpret_cast<ull*>(outr + c) = U[j].rp;
            *reinterpret_cast<ull*>(outi + c) = U[j].ip;
        }
    }
}

// ---------------------------------------------------------------------------
// Kernel B: gates on complex bits 13..21 (angles 8..0). In-place on out.
// Tile = 16 contiguous (bits 0-3, passive) x 512 strided h (bits 13-21).
// 512 threads, 64KB dyn smem; unit u = (h<<3)|(uq<<1)|ulo holds complex
// (h, lo = 4uq+2ulo+{0,1}) packed pair-planar. 64B/h/plane global rows.
// Phases: fill+gates(h7,h8) |F| h0-2 |h| h3-5 |h| drain+gate(h6)+store.
// ---------------------------------------------------------------------------
__global__ void __launch_bounds__(512, 2) gateB(float* __restrict__ dr,
                                                float* __restrict__ di,
                                                const float* __restrict__ ang)
{
    extern __shared__ ulonglong2 sm[];        // 4096 units = 64KB
    __shared__ float sc[22], ss[22];
    const int t = threadIdx.x;
    const unsigned base = (unsigned)blockIdx.x << 4;   // k bits 4-12

    MAKE_COEFS(ang, sc, ss, t);

    UP U[8];

    // ---- fill + gates h7 (bit 20, angle 1), h8 (bit 21, angle 0) ----
    {
        const int uq = t & 3;                 // which float4 of the 64B row
        const int hm = t >> 2;                // h bits 0..6
#pragma unroll
        for (int j = 0; j < 4; ++j) {         // j = (h8<<1)|h7; unit reg = 2j+ulo
            unsigned h = ((unsigned)j << 7) | (unsigned)hm;
            unsigned g = (h << 13) + base + 4u * (unsigned)uq;
            float4 R = *reinterpret_cast<const float4*>(dr + g);
            float4 I = *reinterpret_cast<const float4*>(di + g);
            U[2*j].rp   = pk2(R.x, R.y); U[2*j].ip   = pk2(I.x, I.y);
            U[2*j+1].rp = pk2(R.z, R.w); U[2*j+1].ip = pk2(I.z, I.w);
        }
        __syncthreads();                      // coefs ready (after LDG issue)
        STAGE(2, 1);                          // h7 (reg bit 1)
        STAGE(4, 0);                          // h8 (reg bit 2)
#pragma unroll
        for (int j = 0; j < 4; ++j)
#pragma unroll
            for (int ulo = 0; ulo < 2; ++ulo)
                sm[SW((j << 10) | (hm << 3) | (uq << 1) | ulo)] =
                    make_ulonglong2(U[2*j+ulo].rp, U[2*j+ulo].ip);
    }
    __syncthreads();                          // fill writes cross CTA halves

    // ---- Rd1: gates h0,h1,h2 (bits 13-15, angles 8,7,6) ----
    {
        const int ul = t & 7, hp = t >> 3;    // hp = h bits 3..8
#pragma unroll
        for (int j = 0; j < 8; ++j) {
            ulonglong2 v = sm[SW((hp << 6) | (j << 3) | ul)];
            U[j].rp = v.x; U[j].ip = v.y;
        }
        STAGE(1, 8); STAGE(2, 7); STAGE(4, 6);
#pragma unroll
        for (int j = 0; j < 8; ++j)
            sm[SW((hp << 6) | (j << 3) | ul)] = make_ulonglong2(U[j].rp, U[j].ip);
    }
    BAR_HALF(t);

    // ---- Rd2: gates h3,h4,h5 (bits 16-18, angles 5,4,3) ----
    {
        const int ul = t & 7, hl = (t >> 3) & 7, ht = t >> 6;  // ht = h bits 6-8
#pragma unroll
        for (int j = 0; j < 8; ++j) {
            ulonglong2 v = sm[SW((ht << 9) | (j << 6) | (hl << 3) | ul)];
            U[j].rp = v.x; U[j].ip = v.y;
        }
        STAGE(1, 5); STAGE(2, 4); STAGE(4, 3);
#pragma unroll
        for (int j = 0; j < 8; ++j)
            sm[SW((ht << 9) | (j << 6) | (hl << 3) | ul)] =
                make_ulonglong2(U[j].rp, U[j].ip);
    }
    BAR_HALF(t);

    // ---- drain: gate h6 (bit 19, angle 2); 64B-row coalesced store ----
    {
        const int uq = t & 3;
        const int hlow = (t >> 2) & 63;       // h bits 0..5
        const int h8 = t >> 8;                // h bit 8
#pragma unroll
        for (int j = 0; j < 4; ++j) {         // j = (h7<<1)|h6
            int h = (h8 << 8) | (j << 6) | hlow;
#pragma unroll
            for (int ulo = 0; ulo < 2; ++ulo) {
                ulonglong2 v = sm[SW((h << 3) | (uq << 1) | ulo)];
                U[2*j+ulo].rp = v.x; U[2*j+ulo].ip = v.y;
            }
        }
        STAGE(2, 2);                          // h6 (reg bit 1)
#pragma unroll
        for (int j = 0; j < 4; ++j) {
            unsigned h = ((unsigned)h8 << 8) | ((unsigned)j << 6) | (unsigned)hlow;
            unsigned g = (h << 13) + base + 4u * (unsigned)uq;
            *reinterpret_cast<ulonglong2*>(dr + g) =
                make_ulonglong2(U[2*j].rp, U[2*j+1].rp);
            *reinterpret_cast<ulonglong2*>(di + g) =
                make_ulonglong2(U[2*j].ip, U[2*j+1].ip);
        }
    }
}

extern "C" void kernel_launch(void* const* d_in, const int* in_sizes, int n_in,
                              void* d_out, int out_size)
{
    const float* xr  = (const float*)d_in[0];
    const float* xi  = (const float*)d_in[1];
    const float* ang = (const float*)d_in[2];
    float* outr = (float*)d_out;
    float* outi = outr + NSTATE;

    const int sh = 4096 * sizeof(ulonglong2);  // 64KB
    cudaFuncSetAttribute(gateA, cudaFuncAttributeMaxDynamicSharedMemorySize, sh);
    cudaFuncSetAttribute(gateB, cudaFuncAttributeMaxDynamicSharedMemorySize, sh);

    // Pass 1: gates on bits 0..12 (input -> out)
    gateA<<<NSTATE / 8192, 512, sh>>>(xr, xi, ang, outr, outi);

    // Pass 2: gates on bits 13..21 (in-place on out)
    gateB<<<NSTATE / 8192, 512, sh>>>(outr, outi, ang);
}

// round 10
// speedup vs baseline: 1.1087x; 1.1087x over previous
#include <cuda_runtime.h>

#define NSTATE (1u << 22)

// swizzle on float4-unit index: bank-column = (u ^ (u>>3)) & 7
__device__ __forceinline__ int SW(int u) { return u ^ ((u >> 3) & 7); }

// half-CTA named barrier (ids 1,2; 256 threads each)
#define BAR_HALF(t) asm volatile("bar.sync %0, 256;" :: "r"(1 + ((t) >> 8)) : "memory")

// one 2x2 rotation butterfly: new = (c*I - i*s*X) * old
__device__ __forceinline__ void gate1(float& r0, float& i0, float& r1, float& i1,
                                      float c, float s)
{
    float nr0 = c * r0 + s * i1;
    float ni0 = c * i0 - s * r1;
    float nr1 = c * r1 + s * i0;
    float ni1 = c * i1 - s * r0;
    r0 = nr0; i0 = ni0; r1 = nr1; i1 = ni1;
}

// gate on a pair of interleaved units (each unit = 2 complex: r0,i0,r1,i1)
__device__ __forceinline__ void gateU(float4& A, float4& B, float c, float s)
{
    gate1(A.x, A.y, B.x, B.y, c, s);
    gate1(A.z, A.w, B.z, B.w, c, s);
}

// gate across two (R,I) float4 pairs, componentwise (4 complex each side)
__device__ __forceinline__ void gateV(float4& Ra, float4& Ia, float4& Rb, float4& Ib,
                                      float c, float s)
{
    gate1(Ra.x, Ia.x, Rb.x, Ib.x, c, s);
    gate1(Ra.y, Ia.y, Rb.y, Ib.y, c, s);
    gate1(Ra.z, Ia.z, Rb.z, Ib.z, c, s);
    gate1(Ra.w, Ia.w, Rb.w, Ib.w, c, s);
}

// per-CTA coefficient table: sc[a]=cos(angle[a]/2), ss[a]=sin(angle[a]/2).
// Complex bit b uses angle index 21-b.
#define MAKE_COEFS(ang, sc, ss, t)                                            \
    do {                                                                      \
        if ((t) < 22) {                                                       \
            float c_, s_;                                                     \
            sincosf(0.5f * __ldg((ang) + (t)), &s_, &c_);                     \
            (sc)[t] = c_; (ss)[t] = s_;                                       \
        }                                                                     \
    } while (0)

// 3 butterfly stages over U[8] with unit strides 1,2,4, angle idxs A0,A1,A2
#define STAGE3(A0, A1, A2)                                                    \
    do {                                                                      \
        float c0 = sc[A0], s0 = ss[A0], c1 = sc[A1], s1 = ss[A1];             \
        float c2 = sc[A2], s2 = ss[A2];                                       \
        _Pragma("unroll")                                                     \
        for (int p_ = 0; p_ < 8; ++p_)                                        \
            if (!(p_ & 1)) gateU(U[p_], U[p_ | 1], c0, s0);                   \
        _Pragma("unroll")                                                     \
        for (int p_ = 0; p_ < 8; ++p_)                                        \
            if (!(p_ & 2)) gateU(U[p_], U[p_ | 2], c1, s1);                   \
        _Pragma("unroll")                                                     \
        for (int p_ = 0; p_ < 8; ++p_)                                        \
            if (!(p_ & 4)) gateU(U[p_], U[p_ | 4], c2, s2);                   \
    } while (0)

// ---------------------------------------------------------------------------
// Kernel A: gates on complex bits 0..12 (angles 21..9).
// Tile = 8192 contiguous complex (64KB smem, 4096 units). 512 threads.
// Phases: fill(bits 0-3) |h| R2(4-6) |h| R3(7-9) |F| drain(10-12)+store.
// ---------------------------------------------------------------------------
__global__ void __launch_bounds__(512, 2) gateA(const float* __restrict__ xr,
                                                const float* __restrict__ xi,
                                                const float* __restrict__ ang,
                                                float* __restrict__ outr,
                                                float* __restrict__ outi)
{
    extern __shared__ float4 sm[];            // 4096 units = 64KB
    __shared__ float sc[22], ss[22];
    const int t = threadIdx.x;
    const unsigned base = (unsigned)blockIdx.x << 13;

    MAKE_COEFS(ang, sc, ss, t);

    // ---- fill: 16 contiguous complex/thread, gate bits 0..3 ----
    {
        float4 R[4], I[4];
        const float4* pr = reinterpret_cast<const float4*>(xr + base) + t * 4;
        const float4* pi = reinterpret_cast<const float4*>(xi + base) + t * 4;
#pragma unroll
        for (int q = 0; q < 4; ++q) { R[q] = pr[q]; I[q] = pi[q]; }

        __syncthreads();                      // coefs ready (after LDG issue)

        float c0 = sc[21], s0 = ss[21], c1 = sc[20], s1 = ss[20];
        float c2 = sc[19], s2 = ss[19], c3 = sc[18], s3 = ss[18];
#pragma unroll
        for (int q = 0; q < 4; ++q) {         // bit 0
            gate1(R[q].x, I[q].x, R[q].y, I[q].y, c0, s0);
            gate1(R[q].z, I[q].z, R[q].w, I[q].w, c0, s0);
        }
#pragma unroll
        for (int q = 0; q < 4; ++q) {         // bit 1
            gate1(R[q].x, I[q].x, R[q].z, I[q].z, c1, s1);
            gate1(R[q].y, I[q].y, R[q].w, I[q].w, c1, s1);
        }
        gateV(R[0], I[0], R[1], I[1], c2, s2);   // bit 2
        gateV(R[2], I[2], R[3], I[3], c2, s2);
        gateV(R[0], I[0], R[2], I[2], c3, s3);   // bit 3
        gateV(R[1], I[1], R[3], I[3], c3, s3);

#pragma unroll
        for (int m = 0; m < 8; ++m) {
            int q = m >> 1;
            float4 u = (m & 1) ? make_float4(R[q].z, I[q].z, R[q].w, I[q].w)
                               : make_float4(R[q].x, I[q].x, R[q].y, I[q].y);
            sm[SW(t * 8 + m)] = u;
        }
    }
    BAR_HALF(t);

    float4 U[8];

    // ---- R2: gates bits 4-6 (unit bits 3-5), angles 17,16,15 ----
    {
        const int lo = t & 7, hi = t >> 3;
#pragma unroll
        for (int j = 0; j < 8; ++j) U[j] = sm[SW((hi << 6) | (j << 3) | lo)];
        STAGE3(17, 16, 15);
#pragma unroll
        for (int j = 0; j < 8; ++j) sm[SW((hi << 6) | (j << 3) | lo)] = U[j];
    }
    BAR_HALF(t);

    // ---- R3: gates bits 7-9 (unit bits 6-8), angles 14,13,12 ----
    {
        const int lo = t & 63, hi = t >> 6;
#pragma unroll
        for (int j = 0; j < 8; ++j) U[j] = sm[SW((hi << 9) | (j << 6) | lo)];
        STAGE3(14, 13, 12);
#pragma unroll
        for (int j = 0; j < 8; ++j) sm[SW((hi << 9) | (j << 6) | lo)] = U[j];
    }
    __syncthreads();                          // drain crosses CTA halves

    // ---- drain: gates bits 10-12 (unit bits 9-11), angles 11,10,9; store ----
    {
#pragma unroll
        for (int j = 0; j < 8; ++j) U[j] = sm[SW((j << 9) | t)];
        STAGE3(11, 10, 9);
#pragma unroll
        for (int j = 0; j < 8; ++j) {
            unsigned c = base + ((unsigned)j << 10) + 2u * (unsigned)t;
            float4 A = U[j];
            *reinterpret_cast<float2*>(outr + c) = make_float2(A.x, A.z);
            *reinterpret_cast<float2*>(outi + c) = make_float2(A.y, A.w);
        }
    }
}

// ---------------------------------------------------------------------------
// Kernel B: gates on complex bits 13..21 (angles 8..0). In-place on out.
// Tile = 16 contiguous (bits 0-3, passive) x 512 strided h (bits 13-21).
// 512 threads, 64KB dyn smem; unit u = (h<<3)|w holds complex (h, lo=2w,2w+1)
// as (r,i,r,i). Each thread owns ONE lo-pair (w = t&7) across 8 h-values, so
// fill and drain each gate 3 h-bits. Global rows 64B, lanes 0-7 cover a row.
// Phases: fill+gates(h6-h8) |F| r1(h0-h2) |h| drain(h3-h5)+store.
// ---------------------------------------------------------------------------
__global__ void __launch_bounds__(512, 2) gateB(float* __restrict__ dr,
                                                float* __restrict__ di,
                                                const float* __restrict__ ang)
{
    extern __shared__ float4 sm[];            // 4096 units = 64KB
    __shared__ float sc[22], ss[22];
    const int t = threadIdx.x;
    const unsigned base = (unsigned)blockIdx.x << 4;   // k bits 4-12

    MAKE_COEFS(ang, sc, ss, t);

    float4 U[8];
    const int w = t & 7;                      // lo-pair slot (lo = 2w, 2w+1)

    // ---- fill + gates h6,h7,h8 (bits 19-21, angles 2,1,0) ----
    {
        const int hm = t >> 3;                // h bits 0..5
#pragma unroll
        for (int j = 0; j < 8; ++j) {         // j = h bits 6-8
            unsigned h = ((unsigned)j << 6) | (unsigned)hm;
            unsigned g = (h << 13) + base + 2u * (unsigned)w;
            float2 R = *reinterpret_cast<const float2*>(dr + g);
            float2 I = *reinterpret_cast<const float2*>(di + g);
            U[j] = make_float4(R.x, I.x, R.y, I.y);
        }
        __syncthreads();                      // coefs ready (after LDG issue)
        STAGE3(2, 1, 0);
#pragma unroll
        for (int j = 0; j < 8; ++j)
            sm[SW((j << 9) | (hm << 3) | w)] = U[j];
    }
    __syncthreads();                          // fill->r1 crosses CTA halves

    // ---- r1: gates h0,h1,h2 (bits 13-15, angles 8,7,6) ----
    {
        const int hh = t >> 3;                // h bits 3..8
#pragma unroll
        for (int j = 0; j < 8; ++j) U[j] = sm[SW((hh << 6) | (j << 3) | w)];
        STAGE3(8, 7, 6);
#pragma unroll
        for (int j = 0; j < 8; ++j) sm[SW((hh << 6) | (j << 3) | w)] = U[j];
    }
    BAR_HALF(t);                              // r1->drain is half-local (u bit 11)

    // ---- drain: gates h3,h4,h5 (bits 16-18, angles 5,4,3); store ----
    {
        const int hb = (t >> 3) & 7;          // h bits 0..2
        const int ht = t >> 6;                // h bits 6..8
#pragma unroll
        for (int j = 0; j < 8; ++j)           // j = h bits 3-5
            U[j] = sm[SW((ht << 9) | (j << 6) | (hb << 3) | w)];
        STAGE3(5, 4, 3);
#pragma unroll
        for (int j = 0; j < 8; ++j) {
            unsigned h = ((unsigned)ht << 6) | ((unsigned)j << 3) | (unsigned)hb;
            unsigned g = (h << 13) + base + 2u * (unsigned)w;
            float4 A = U[j];
            *reinterpret_cast<float2*>(dr + g) = make_float2(A.x, A.z);
            *reinterpret_cast<float2*>(di + g) = make_float2(A.y, A.w);
        }
    }
}

extern "C" void kernel_launch(void* const* d_in, const int* in_sizes, int n_in,
                              void* d_out, int out_size)
{
    const float* xr  = (const float*)d_in[0];
    const float* xi  = (const float*)d_in[1];
    const float* ang = (const float*)d_in[2];
    float* outr = (float*)d_out;
    float* outi = outr + NSTATE;

    const int sh = 4096 * sizeof(float4);     // 64KB
    cudaFuncSetAttribute(gateA, cudaFuncAttributeMaxDynamicSharedMemorySize, sh);
    cudaFuncSetAttribute(gateB, cudaFuncAttributeMaxDynamicSharedMemorySize, sh);

    // Pass 1: gates on bits 0..12 (input -> out)
    gateA<<<NSTATE / 8192, 512, sh>>>(xr, xi, ang, outr, outi);

    // Pass 2: gates on bits 13..21 (in-place on out)
    gateB<<<NSTATE / 8192, 512, sh>>>(outr, outi, ang);
}